// round 10
// baseline (speedup 1.0000x reference)
#include <cuda_runtime.h>
#include <math.h>

#define NN_MAX 50000
#define S_IN 128
#define S_OUT 128
#define K_MERGED 153
#define EPSS 1e-8f
#define NREP 8
#define TILE 32
#define MROW 36   // mT2 row (32 nodes + 4 pad), 144B = 16B-aligned

// Scratch (static device globals)
__device__ float g_vdf[NN_MAX * 12];
__device__ float g_acc[(size_t)NREP * NN_MAX * 16];
__device__ float g_fold[NN_MAX * 12];
__device__ float g_WsoT[K_MERGED * 128];   // [k][col]
__device__ float g_WgT[128 * 16];          // blocked: [k4][o][kk], k=k4*4+kk

// ---------------------------------------------------------------------------
// K1: zero accumulators, compute vdf, transpose W_so and W_g
// ---------------------------------------------------------------------------
__global__ void k_pre(const float* __restrict__ vector,
                      const float* __restrict__ W_df,
                      const float* __restrict__ W_so,
                      const float* __restrict__ W_g,
                      int n_nodes)
{
    int tid = blockIdx.x * blockDim.x + threadIdx.x;

    size_t nzero4 = (size_t)NREP * n_nodes * 4;
    if ((size_t)tid < nzero4)
        reinterpret_cast<float4*>(g_acc)[tid] = make_float4(0.f, 0.f, 0.f, 0.f);

    if (tid < K_MERGED * 128) {
        int k = tid >> 7, o = tid & 127;
        g_WsoT[tid] = W_so[o * K_MERGED + k];
    }
    if (tid < 2048) {
        int kk = tid & 3, o = (tid >> 2) & 15, k4 = tid >> 6;
        g_WgT[tid] = W_g[o * 128 + k4 * 4 + kk];
    }

    if (tid >= n_nodes) return;
    int n = tid;

    float v[48];
    const float4* vp = reinterpret_cast<const float4*>(vector + (size_t)n * 48);
#pragma unroll
    for (int q = 0; q < 12; q++) {
        float4 f = vp[q];
        v[q*4+0] = f.x; v[q*4+1] = f.y; v[q*4+2] = f.z; v[q*4+3] = f.w;
    }
#pragma unroll
    for (int j = 0; j < 3; j++) {
        float r0 = 0.f, r1 = 0.f, r2 = 0.f;
#pragma unroll
        for (int i = 0; i < 16; i++) {
            float x = v[i*3 + j];
            r0 += x * __ldg(&W_df[i]);
            r1 += x * __ldg(&W_df[16 + i]);
            r2 += x * __ldg(&W_df[32 + i]);
        }
        g_vdf[(size_t)n*12 + j*3 + 0] = r0;
        g_vdf[(size_t)n*12 + j*3 + 1] = r1;
        g_vdf[(size_t)n*12 + j*3 + 2] = r2;
    }
}

// ---------------------------------------------------------------------------
// K2: per-edge rotation + replicated scatter-add (replica = e & 7)
// ---------------------------------------------------------------------------
__global__ void k_edge(const int* __restrict__ ei,
                       const float* __restrict__ frames,
                       int n_edges, int n_nodes)
{
    int e = blockIdx.x * blockDim.x + threadIdx.x;
    if (e >= n_edges) return;

    int row = ei[e];

    const float4* vp = reinterpret_cast<const float4*>(g_vdf + (size_t)row * 12);
    float4 va = vp[0], vb = vp[1], vc = vp[2];
    float v[9] = { va.x, va.y, va.z, va.w, vb.x, vb.y, vb.z, vb.w, vc.x };

    const float* f = frames + (size_t)e * 9;
    float F[9];
#pragma unroll
    for (int i = 0; i < 9; i++) F[i] = __ldg(&f[i]);

    float loc[9];
#pragma unroll
    for (int x = 0; x < 3; x++)
#pragma unroll
        for (int c = 0; c < 3; c++)
            loc[c*3 + x] = F[x*3+0]*v[0+c] + F[x*3+1]*v[3+c] + F[x*3+2]*v[6+c];

    int rep = e & (NREP - 1);
    float* dst = g_acc + ((size_t)rep * n_nodes + row) * 16;
    asm volatile("red.global.add.v4.f32 [%0], {%1,%2,%3,%4};" ::
                 "l"(dst), "f"(loc[0]), "f"(loc[1]), "f"(loc[2]), "f"(loc[3]) : "memory");
    asm volatile("red.global.add.v4.f32 [%0], {%1,%2,%3,%4};" ::
                 "l"(dst+4), "f"(loc[4]), "f"(loc[5]), "f"(loc[6]), "f"(loc[7]) : "memory");
    asm volatile("red.global.add.v2.f32 [%0], {%1,%2};" ::
                 "l"(dst+8), "f"(loc[8]), "f"(1.0f) : "memory");
}

// ---------------------------------------------------------------------------
// K2b: fold replicas -> meaned 9 values per node
// ---------------------------------------------------------------------------
__global__ void k_fold(int n_nodes)
{
    int n = blockIdx.x * blockDim.x + threadIdx.x;
    if (n >= n_nodes) return;

    float sum[9] = {0,0,0,0,0,0,0,0,0};
    float cnt = 0.f;
#pragma unroll
    for (int r = 0; r < NREP; r++) {
        const float* a = g_acc + ((size_t)r * n_nodes + n) * 16;
        float4 p0 = reinterpret_cast<const float4*>(a)[0];
        float4 p1 = reinterpret_cast<const float4*>(a)[1];
        float2 p2 = reinterpret_cast<const float2*>(a)[4];
        sum[0] += p0.x; sum[1] += p0.y; sum[2] += p0.z; sum[3] += p0.w;
        sum[4] += p1.x; sum[5] += p1.y; sum[6] += p1.z; sum[7] += p1.w;
        sum[8] += p2.x; cnt += p2.y;
    }
    float inv = 1.0f / fmaxf(cnt, 1.0f);
    float* o = g_fold + (size_t)n * 12;
#pragma unroll
    for (int c = 0; c < 9; c++) o[c] = sum[c] * inv;
    o[9] = 0.f; o[10] = 0.f; o[11] = 0.f;
}

// ---------------------------------------------------------------------------
// K3: node MLP. 32-node tiles; warp = 64 cols x 8 nodes (2 cols/lane).
// Phase B/E vectorized (LDS.128); balanced persistent grid.
// ---------------------------------------------------------------------------
__global__ __launch_bounds__(256, 4) void k_post(
    const float* __restrict__ scalar, const float* __restrict__ vector,
    const float* __restrict__ W_down, const float* __restrict__ b_so,
    const float* __restrict__ W_up,
    const float* __restrict__ b_g,
    float* __restrict__ out_s, float* __restrict__ out_v, int n_nodes)
{
    const int t = threadIdx.x;
    const int lane = t & 31;
    const int wid = t >> 5;

    // GEMM assignment: 2 cols, 8 nodes
    const int colh = wid & 1;
    const int nd0g = (wid >> 1) * 8;
    const int c0 = colh * 64 + lane * 2;

    const float2 bso2 = *reinterpret_cast<const float2*>(b_so + c0);

    // gates: o = t&15; nodes ndA = t>>4 and ndA+16
    const int go = t & 15;
    const int ndA = t >> 4;
    const float bg = b_g[go];

    __shared__ __align__(16) float mT2[K_MERGED * MROW];  // k-major merged
    __shared__ __align__(16) float uni[TILE * 132];       // ssm (pad 132) ∪ vecs (pad 52)
    __shared__ __align__(16) float vh[TILE * 52];
    __shared__ float gsig[TILE * 16];
    __shared__ float sWdown[256], sWup[256];

    float* const ssm  = uni;   // [nd*132 + col]
    float* const vecs = uni;   // [nd*52 + c]

    sWdown[t] = W_down[t];
    sWup[t]   = W_up[t];
    __syncthreads();

    const int ntiles = (n_nodes + TILE - 1) / TILE;
    const int acol = t >> 1, ahalf = t & 1;    // phase A mapping

    for (int tile = blockIdx.x; tile < ntiles; tile += gridDim.x) {
        const int nb = tile * TILE;

        // ===== Phase A: scalar -> mT2 rows, vecs, sh rows =====
#pragma unroll 4
        for (int i = 0; i < 16; i++) {
            int nd = ahalf * 16 + i;
            int node = nb + nd;
            float p = (node < n_nodes) ? scalar[(size_t)node * 128 + acol] : 0.f;
            mT2[acol * MROW + nd] = p;
        }
#pragma unroll
        for (int r = 0; r < 2; r++) {
            int idx = t + 256 * r;
            if (idx < 384) {
                int nd = idx / 12, q = idx - nd * 12;
                int node = nb + nd;
                float4 f = (node < n_nodes)
                    ? reinterpret_cast<const float4*>(vector)[(size_t)node * 12 + q]
                    : make_float4(0.f, 0.f, 0.f, 0.f);
                *reinterpret_cast<float4*>(vecs + nd * 52 + q * 4) = f;
            }
        }
        {
            int nd = t & 31, node = nb + nd;
            for (int c = t >> 5; c < 9; c += 8) {
                float v = (node < n_nodes) ? g_fold[(size_t)node * 12 + c] : 0.f;
                mT2[(144 + c) * MROW + nd] = v;
            }
        }
        __syncthreads();

        // ===== Phase B: vh + vnorm rows (vectorized reads) =====
        {
            int nd = t >> 3, h2 = (t & 7) * 2;
            const float4* vp4 = reinterpret_cast<const float4*>(vecs + nd * 52);
            float a[2][3] = {{0.f,0.f,0.f},{0.f,0.f,0.f}};
            float v[24];
            // first 8 input channels (floats 0..23)
#pragma unroll
            for (int q = 0; q < 6; q++) {
                float4 f = vp4[q];
                v[q*4+0]=f.x; v[q*4+1]=f.y; v[q*4+2]=f.z; v[q*4+3]=f.w;
            }
#pragma unroll
            for (int hh = 0; hh < 2; hh++) {
                int h = h2 + hh;
#pragma unroll
                for (int i = 0; i < 8; i++) {
                    float wd = sWdown[h * 16 + i];
                    a[hh][0] += v[i*3+0] * wd;
                    a[hh][1] += v[i*3+1] * wd;
                    a[hh][2] += v[i*3+2] * wd;
                }
            }
            // last 8 input channels (floats 24..47)
#pragma unroll
            for (int q = 0; q < 6; q++) {
                float4 f = vp4[6+q];
                v[q*4+0]=f.x; v[q*4+1]=f.y; v[q*4+2]=f.z; v[q*4+3]=f.w;
            }
#pragma unroll
            for (int hh = 0; hh < 2; hh++) {
                int h = h2 + hh;
#pragma unroll
                for (int i = 8; i < 16; i++) {
                    float wd = sWdown[h * 16 + i];
                    a[hh][0] += v[i*3+0-24] * wd;
                    a[hh][1] += v[i*3+1-24] * wd;
                    a[hh][2] += v[i*3+2-24] * wd;
                }
            }
            __syncthreads();   // vecs (uni) reads done before vh/mT2 writes race? no race: vh/mT2 distinct from uni. But ssm aliases uni later; sync below suffices.
#pragma unroll
            for (int hh = 0; hh < 2; hh++) {
                int h = h2 + hh;
                vh[nd * 52 +  0 + h] = a[hh][0];
                vh[nd * 52 + 16 + h] = a[hh][1];
                vh[nd * 52 + 32 + h] = a[hh][2];
                mT2[(128 + h) * MROW + nd] =
                    sqrtf(a[hh][0]*a[hh][0] + a[hh][1]*a[hh][1] + a[hh][2]*a[hh][2] + EPSS);
            }
        }
        __syncthreads();

        // ===== Phase C: outer-product GEMM (2 cols x 8 nodes per lane) =====
        {
            unsigned long long a00=0ULL,a01=0ULL,a02=0ULL,a03=0ULL,
                               a10=0ULL,a11=0ULL,a12=0ULL,a13=0ULL;
            const float* wbase = g_WsoT + c0;
            const float* mbase = mT2 + nd0g;
#pragma unroll 3
            for (int k = 0; k < K_MERGED; k++) {
                float2 w = __ldg(reinterpret_cast<const float2*>(wbase + (size_t)k * 128));
                ulonglong2 mA = *reinterpret_cast<const ulonglong2*>(mbase + (size_t)k * MROW);
                ulonglong2 mB = *reinterpret_cast<const ulonglong2*>(mbase + (size_t)k * MROW + 4);
                unsigned long long wd0, wd1;
                asm("mov.b64 %0, {%1, %1};" : "=l"(wd0) : "f"(w.x));
                asm("mov.b64 %0, {%1, %1};" : "=l"(wd1) : "f"(w.y));
                asm("fma.rn.f32x2 %0, %1, %2, %0;" : "+l"(a00) : "l"(wd0), "l"(mA.x));
                asm("fma.rn.f32x2 %0, %1, %2, %0;" : "+l"(a01) : "l"(wd0), "l"(mA.y));
                asm("fma.rn.f32x2 %0, %1, %2, %0;" : "+l"(a02) : "l"(wd0), "l"(mB.x));
                asm("fma.rn.f32x2 %0, %1, %2, %0;" : "+l"(a03) : "l"(wd0), "l"(mB.y));
                asm("fma.rn.f32x2 %0, %1, %2, %0;" : "+l"(a10) : "l"(wd1), "l"(mA.x));
                asm("fma.rn.f32x2 %0, %1, %2, %0;" : "+l"(a11) : "l"(wd1), "l"(mA.y));
                asm("fma.rn.f32x2 %0, %1, %2, %0;" : "+l"(a12) : "l"(wd1), "l"(mB.x));
                asm("fma.rn.f32x2 %0, %1, %2, %0;" : "+l"(a13) : "l"(wd1), "l"(mB.y));
            }
            unsigned long long acc0[4] = {a00,a01,a02,a03};
            unsigned long long acc1[4] = {a10,a11,a12,a13};
#pragma unroll
            for (int p = 0; p < 4; p++) {
                float lo0, hi0, lo1, hi1;
                asm("mov.b64 {%0, %1}, %2;" : "=f"(lo0), "=f"(hi0) : "l"(acc0[p]));
                asm("mov.b64 {%0, %1}, %2;" : "=f"(lo1), "=f"(hi1) : "l"(acc1[p]));
                float sv00 = lo0 + bso2.x, sv01 = lo1 + bso2.y;
                float sv10 = hi0 + bso2.x, sv11 = hi1 + bso2.y;
                float s00 = sv00 / (1.0f + __expf(-sv00));
                float s01 = sv01 / (1.0f + __expf(-sv01));
                float s10 = sv10 / (1.0f + __expf(-sv10));
                float s11 = sv11 / (1.0f + __expf(-sv11));
                *reinterpret_cast<float2*>(ssm + (nd0g + 2*p    ) * 132 + c0) =
                    make_float2(s00, s01);
                *reinterpret_cast<float2*>(ssm + (nd0g + 2*p + 1) * 132 + c0) =
                    make_float2(s10, s11);
            }
        }
        __syncthreads();

        // ===== Phase D: gates (blocked transposed weights) + out_s =====
        {
            float pA = 0.f, pB = 0.f;
            const float4* wgt = reinterpret_cast<const float4*>(g_WgT + go * 4);
            const float4* sA4 = reinterpret_cast<const float4*>(ssm + ndA * 132);
            const float4* sB4 = reinterpret_cast<const float4*>(ssm + (ndA + 16) * 132);
#pragma unroll 8
            for (int k4 = 0; k4 < 32; k4++) {
                float4 w = __ldg(wgt + k4 * 16);
                float4 xa = sA4[k4];
                float4 xb = sB4[k4];
                pA += w.x*xa.x + w.y*xa.y + w.z*xa.z + w.w*xa.w;
                pB += w.x*xb.x + w.y*xb.y + w.z*xb.z + w.w*xb.w;
            }
            gsig[ndA * 16 + go]        = 1.0f / (1.0f + __expf(-(pA + bg)));
            gsig[(ndA + 16) * 16 + go] = 1.0f / (1.0f + __expf(-(pB + bg)));
        }
#pragma unroll
        for (int r = 0; r < 4; r++) {
            int nd = wid + 8 * r;
            int node = nb + nd;
            float4 v = *reinterpret_cast<const float4*>(ssm + nd * 132 + lane * 4);
            if (node < n_nodes)
                reinterpret_cast<float4*>(out_s + (size_t)node * 128)[lane] = v;
        }
        __syncthreads();

        // ===== Phase E: gated vector output (vectorized) =====
#pragma unroll
        for (int r = 0; r < 6; r++) {
            int i = t + 256 * r;
            int nd = i / 48, j = i - nd * 48;
            int o = j / 3, x = j - o * 3;
            const float4* vh4 = reinterpret_cast<const float4*>(vh + nd * 52 + x * 16);
            const float4* wu4 = reinterpret_cast<const float4*>(sWup + o * 16);
            float a = 0.f;
#pragma unroll
            for (int q = 0; q < 4; q++) {
                float4 vv = vh4[q];
                float4 wu = wu4[q];
                a += vv.x*wu.x + vv.y*wu.y + vv.z*wu.z + vv.w*wu.w;
            }
            int node = nb + nd;
            if (node < n_nodes)
                out_v[(size_t)node * 48 + j] = a * gsig[nd * 16 + o];
        }
        __syncthreads();
    }
}

extern "C" void kernel_launch(void* const* d_in, const int* in_sizes, int n_in,
                              void* d_out, int out_size) {
    const float* scalar = (const float*)d_in[0];
    const float* vector = (const float*)d_in[1];
    const int*   ei     = (const int*)d_in[2];
    const float* frames = (const float*)d_in[3];
    const float* W_down = (const float*)d_in[4];
    const float* W_df   = (const float*)d_in[5];
    const float* W_so   = (const float*)d_in[6];
    const float* b_so   = (const float*)d_in[7];
    const float* W_up   = (const float*)d_in[8];
    const float* W_g    = (const float*)d_in[9];
    const float* b_g    = (const float*)d_in[10];

    int n = in_sizes[0] / S_IN;
    int e = in_sizes[2] / 2;

    float* out_s = (float*)d_out;
    float* out_v = out_s + (size_t)n * S_OUT;

    size_t pre_jobs = (size_t)NREP * n * 4;
    if (pre_jobs < (size_t)n) pre_jobs = n;
    if (pre_jobs < (size_t)K_MERGED * 128) pre_jobs = K_MERGED * 128;

    // balanced persistent grid: all CTAs do the same number of tiles
    int ntiles = (n + TILE - 1) / TILE;
    int cap = 592;                       // 4 CTAs/SM x 148 SMs
    int waves = (ntiles + cap - 1) / cap;
    int grid = (ntiles + waves - 1) / waves;

    k_pre<<<(int)((pre_jobs + 255) / 256), 256>>>(vector, W_df, W_so, W_g, n);
    k_edge<<<(e + 255) / 256, 256>>>(ei, frames, e, n);
    k_fold<<<(n + 255) / 256, 256>>>(n);
    k_post<<<grid, 256>>>(scalar, vector, W_down, b_so, W_up, b_g,
                          out_s, out_v, n);
}

// round 11
// speedup vs baseline: 1.0969x; 1.0969x over previous
#include <cuda_runtime.h>
#include <math.h>

#define NN_MAX 50000
#define S_IN 128
#define S_OUT 128
#define K_MERGED 153
#define EPSS 1e-8f
#define NREP 8
#define TILE 32
#define MROW 36   // mT2 row (32 nodes + 4 pad), 144B = 16B-aligned

// Scratch (static device globals)
__device__ float g_vdf[NN_MAX * 12];
__device__ float g_acc[(size_t)NREP * NN_MAX * 16];
__device__ float g_fold[NN_MAX * 12];
__device__ float g_WsoT[K_MERGED * 128];   // [k][col]
__device__ float g_WgT[128 * 16];          // blocked: [k4][o][kk], k=k4*4+kk
__device__ unsigned int g_ticket;          // dynamic tile counter (zeroed in k_pre)

// ---------------------------------------------------------------------------
// K1: zero accumulators + ticket, compute vdf, transpose W_so and W_g
// ---------------------------------------------------------------------------
__global__ void k_pre(const float* __restrict__ vector,
                      const float* __restrict__ W_df,
                      const float* __restrict__ W_so,
                      const float* __restrict__ W_g,
                      int n_nodes)
{
    int tid = blockIdx.x * blockDim.x + threadIdx.x;

    if (tid == 0) g_ticket = 0u;

    size_t nzero4 = (size_t)NREP * n_nodes * 4;
    if ((size_t)tid < nzero4)
        reinterpret_cast<float4*>(g_acc)[tid] = make_float4(0.f, 0.f, 0.f, 0.f);

    if (tid < K_MERGED * 128) {
        int k = tid >> 7, o = tid & 127;
        g_WsoT[tid] = W_so[o * K_MERGED + k];
    }
    if (tid < 2048) {
        int kk = tid & 3, o = (tid >> 2) & 15, k4 = tid >> 6;
        g_WgT[tid] = W_g[o * 128 + k4 * 4 + kk];
    }

    if (tid >= n_nodes) return;
    int n = tid;

    float v[48];
    const float4* vp = reinterpret_cast<const float4*>(vector + (size_t)n * 48);
#pragma unroll
    for (int q = 0; q < 12; q++) {
        float4 f = vp[q];
        v[q*4+0] = f.x; v[q*4+1] = f.y; v[q*4+2] = f.z; v[q*4+3] = f.w;
    }
#pragma unroll
    for (int j = 0; j < 3; j++) {
        float r0 = 0.f, r1 = 0.f, r2 = 0.f;
#pragma unroll
        for (int i = 0; i < 16; i++) {
            float x = v[i*3 + j];
            r0 += x * __ldg(&W_df[i]);
            r1 += x * __ldg(&W_df[16 + i]);
            r2 += x * __ldg(&W_df[32 + i]);
        }
        g_vdf[(size_t)n*12 + j*3 + 0] = r0;
        g_vdf[(size_t)n*12 + j*3 + 1] = r1;
        g_vdf[(size_t)n*12 + j*3 + 2] = r2;
    }
}

// ---------------------------------------------------------------------------
// K2: per-edge rotation + replicated scatter-add (replica = e & 7)
// ---------------------------------------------------------------------------
__global__ void k_edge(const int* __restrict__ ei,
                       const float* __restrict__ frames,
                       int n_edges, int n_nodes)
{
    int e = blockIdx.x * blockDim.x + threadIdx.x;
    if (e >= n_edges) return;

    int row = ei[e];

    const float4* vp = reinterpret_cast<const float4*>(g_vdf + (size_t)row * 12);
    float4 va = vp[0], vb = vp[1], vc = vp[2];
    float v[9] = { va.x, va.y, va.z, va.w, vb.x, vb.y, vb.z, vb.w, vc.x };

    const float* f = frames + (size_t)e * 9;
    float F[9];
#pragma unroll
    for (int i = 0; i < 9; i++) F[i] = __ldg(&f[i]);

    float loc[9];
#pragma unroll
    for (int x = 0; x < 3; x++)
#pragma unroll
        for (int c = 0; c < 3; c++)
            loc[c*3 + x] = F[x*3+0]*v[0+c] + F[x*3+1]*v[3+c] + F[x*3+2]*v[6+c];

    int rep = e & (NREP - 1);
    float* dst = g_acc + ((size_t)rep * n_nodes + row) * 16;
    asm volatile("red.global.add.v4.f32 [%0], {%1,%2,%3,%4};" ::
                 "l"(dst), "f"(loc[0]), "f"(loc[1]), "f"(loc[2]), "f"(loc[3]) : "memory");
    asm volatile("red.global.add.v4.f32 [%0], {%1,%2,%3,%4};" ::
                 "l"(dst+4), "f"(loc[4]), "f"(loc[5]), "f"(loc[6]), "f"(loc[7]) : "memory");
    asm volatile("red.global.add.v2.f32 [%0], {%1,%2};" ::
                 "l"(dst+8), "f"(loc[8]), "f"(1.0f) : "memory");
}

// ---------------------------------------------------------------------------
// K2b: fold replicas -> meaned 9 values per node
// ---------------------------------------------------------------------------
__global__ void k_fold(int n_nodes)
{
    int n = blockIdx.x * blockDim.x + threadIdx.x;
    if (n >= n_nodes) return;

    float sum[9] = {0,0,0,0,0,0,0,0,0};
    float cnt = 0.f;
#pragma unroll
    for (int r = 0; r < NREP; r++) {
        const float* a = g_acc + ((size_t)r * n_nodes + n) * 16;
        float4 p0 = reinterpret_cast<const float4*>(a)[0];
        float4 p1 = reinterpret_cast<const float4*>(a)[1];
        float2 p2 = reinterpret_cast<const float2*>(a)[4];
        sum[0] += p0.x; sum[1] += p0.y; sum[2] += p0.z; sum[3] += p0.w;
        sum[4] += p1.x; sum[5] += p1.y; sum[6] += p1.z; sum[7] += p1.w;
        sum[8] += p2.x; cnt += p2.y;
    }
    float inv = 1.0f / fmaxf(cnt, 1.0f);
    float* o = g_fold + (size_t)n * 12;
#pragma unroll
    for (int c = 0; c < 9; c++) o[c] = sum[c] * inv;
    o[9] = 0.f; o[10] = 0.f; o[11] = 0.f;
}

// ---------------------------------------------------------------------------
// K3: node MLP. 32-node tiles; warp = 64 cols x 8 nodes (2 cols/lane):
// weight LDG.64, merged via 16B LDS broadcasts, 2 MOV dup, 8 FFMA2/k.
// Dynamic ticket-based tile scheduling for SM-level balance.
// ---------------------------------------------------------------------------
__global__ __launch_bounds__(256, 4) void k_post(
    const float* __restrict__ scalar, const float* __restrict__ vector,
    const float* __restrict__ W_down, const float* __restrict__ b_so,
    const float* __restrict__ W_up,
    const float* __restrict__ b_g,
    float* __restrict__ out_s, float* __restrict__ out_v, int n_nodes)
{
    const int t = threadIdx.x;
    const int lane = t & 31;
    const int wid = t >> 5;

    // GEMM assignment: 2 cols, 8 nodes
    const int colh = wid & 1;
    const int nd0g = (wid >> 1) * 8;
    const int c0 = colh * 64 + lane * 2;

    const float2 bso2 = *reinterpret_cast<const float2*>(b_so + c0);

    // gates: o = t&15; nodes ndA = t>>4 and ndA+16
    const int go = t & 15;
    const int ndA = t >> 4;
    const float bg = b_g[go];

    __shared__ __align__(16) float mT2[K_MERGED * MROW];  // k-major merged
    __shared__ __align__(16) float uni[TILE * 132];       // ssm (pad 132) ∪ vecs
    __shared__ float vh[TILE * 50];
    __shared__ float gsig[TILE * 16];
    __shared__ float sWdown[256], sWup[256];
    __shared__ int s_tile;

    float* const ssm  = uni;   // [nd*132 + col]
    float* const vecs = uni;   // [nd*52 + c]

    sWdown[t] = W_down[t];
    sWup[t]   = W_up[t];
    __syncthreads();

    const int ntiles = (n_nodes + TILE - 1) / TILE;
    const int acol = t >> 1, ahalf = t & 1;    // phase A mapping

    while (true) {
        if (t == 0) s_tile = (int)atomicAdd(&g_ticket, 1u);
        __syncthreads();
        const int tile = s_tile;
        if (tile >= ntiles) break;
        const int nb = tile * TILE;

        // ===== Phase A: scalar -> mT2 rows, vecs, sh rows =====
#pragma unroll 4
        for (int i = 0; i < 16; i++) {
            int nd = ahalf * 16 + i;
            int node = nb + nd;
            float p = (node < n_nodes) ? scalar[(size_t)node * 128 + acol] : 0.f;
            mT2[acol * MROW + nd] = p;
        }
#pragma unroll
        for (int r = 0; r < 2; r++) {
            int idx = t + 256 * r;
            if (idx < 384) {
                int nd = idx / 12, q = idx - nd * 12;
                int node = nb + nd;
                float4 f = (node < n_nodes)
                    ? reinterpret_cast<const float4*>(vector)[(size_t)node * 12 + q]
                    : make_float4(0.f, 0.f, 0.f, 0.f);
                *reinterpret_cast<float4*>(vecs + nd * 52 + q * 4) = f;
            }
        }
        {
            int nd = t & 31, node = nb + nd;
            for (int c = t >> 5; c < 9; c += 8) {
                float v = (node < n_nodes) ? g_fold[(size_t)node * 12 + c] : 0.f;
                mT2[(144 + c) * MROW + nd] = v;
            }
        }
        __syncthreads();

        // ===== Phase B: vh + vnorm rows =====
        {
            int nd = t >> 3, h2 = (t & 7) * 2;
#pragma unroll
            for (int hh = 0; hh < 2; hh++) {
                int h = h2 + hh;
                float a0 = 0.f, a1 = 0.f, a2 = 0.f;
#pragma unroll
                for (int i = 0; i < 16; i++) {
                    float wd = sWdown[h * 16 + i];
                    a0 += vecs[nd * 52 + i * 3 + 0] * wd;
                    a1 += vecs[nd * 52 + i * 3 + 1] * wd;
                    a2 += vecs[nd * 52 + i * 3 + 2] * wd;
                }
                vh[nd * 50 +  0 + h] = a0;
                vh[nd * 50 + 16 + h] = a1;
                vh[nd * 50 + 32 + h] = a2;
                mT2[(128 + h) * MROW + nd] = sqrtf(a0*a0 + a1*a1 + a2*a2 + EPSS);
            }
        }
        __syncthreads();

        // ===== Phase C: outer-product GEMM (2 cols x 8 nodes per lane) =====
        {
            unsigned long long a00=0ULL,a01=0ULL,a02=0ULL,a03=0ULL,
                               a10=0ULL,a11=0ULL,a12=0ULL,a13=0ULL;
            const float* wbase = g_WsoT + c0;
            const float* mbase = mT2 + nd0g;
#pragma unroll 3
            for (int k = 0; k < K_MERGED; k++) {
                float2 w = __ldg(reinterpret_cast<const float2*>(wbase + (size_t)k * 128));
                ulonglong2 mA = *reinterpret_cast<const ulonglong2*>(mbase + (size_t)k * MROW);
                ulonglong2 mB = *reinterpret_cast<const ulonglong2*>(mbase + (size_t)k * MROW + 4);
                unsigned long long wd0, wd1;
                asm("mov.b64 %0, {%1, %1};" : "=l"(wd0) : "f"(w.x));
                asm("mov.b64 %0, {%1, %1};" : "=l"(wd1) : "f"(w.y));
                asm("fma.rn.f32x2 %0, %1, %2, %0;" : "+l"(a00) : "l"(wd0), "l"(mA.x));
                asm("fma.rn.f32x2 %0, %1, %2, %0;" : "+l"(a01) : "l"(wd0), "l"(mA.y));
                asm("fma.rn.f32x2 %0, %1, %2, %0;" : "+l"(a02) : "l"(wd0), "l"(mB.x));
                asm("fma.rn.f32x2 %0, %1, %2, %0;" : "+l"(a03) : "l"(wd0), "l"(mB.y));
                asm("fma.rn.f32x2 %0, %1, %2, %0;" : "+l"(a10) : "l"(wd1), "l"(mA.x));
                asm("fma.rn.f32x2 %0, %1, %2, %0;" : "+l"(a11) : "l"(wd1), "l"(mA.y));
                asm("fma.rn.f32x2 %0, %1, %2, %0;" : "+l"(a12) : "l"(wd1), "l"(mB.x));
                asm("fma.rn.f32x2 %0, %1, %2, %0;" : "+l"(a13) : "l"(wd1), "l"(mB.y));
            }
            // epilogue: acc halves = nodes (nd0g+2p, nd0g+2p+1), cols c0,c0+1
            unsigned long long acc0[4] = {a00,a01,a02,a03};
            unsigned long long acc1[4] = {a10,a11,a12,a13};
#pragma unroll
            for (int p = 0; p < 4; p++) {
                float lo0, hi0, lo1, hi1;
                asm("mov.b64 {%0, %1}, %2;" : "=f"(lo0), "=f"(hi0) : "l"(acc0[p]));
                asm("mov.b64 {%0, %1}, %2;" : "=f"(lo1), "=f"(hi1) : "l"(acc1[p]));
                float sv00 = lo0 + bso2.x, sv01 = lo1 + bso2.y;
                float sv10 = hi0 + bso2.x, sv11 = hi1 + bso2.y;
                float s00 = sv00 / (1.0f + __expf(-sv00));
                float s01 = sv01 / (1.0f + __expf(-sv01));
                float s10 = sv10 / (1.0f + __expf(-sv10));
                float s11 = sv11 / (1.0f + __expf(-sv11));
                *reinterpret_cast<float2*>(ssm + (nd0g + 2*p    ) * 132 + c0) =
                    make_float2(s00, s01);
                *reinterpret_cast<float2*>(ssm + (nd0g + 2*p + 1) * 132 + c0) =
                    make_float2(s10, s11);
            }
        }
        __syncthreads();

        // ===== Phase D: gates (blocked transposed weights) + out_s =====
        {
            float pA = 0.f, pB = 0.f;
            const float4* wgt = reinterpret_cast<const float4*>(g_WgT + go * 4);
            const float4* sA4 = reinterpret_cast<const float4*>(ssm + ndA * 132);
            const float4* sB4 = reinterpret_cast<const float4*>(ssm + (ndA + 16) * 132);
#pragma unroll 8
            for (int k4 = 0; k4 < 32; k4++) {
                float4 w = __ldg(wgt + k4 * 16);
                float4 xa = sA4[k4];
                float4 xb = sB4[k4];
                pA += w.x*xa.x + w.y*xa.y + w.z*xa.z + w.w*xa.w;
                pB += w.x*xb.x + w.y*xb.y + w.z*xb.z + w.w*xb.w;
            }
            gsig[ndA * 16 + go]        = 1.0f / (1.0f + __expf(-(pA + bg)));
            gsig[(ndA + 16) * 16 + go] = 1.0f / (1.0f + __expf(-(pB + bg)));
        }
#pragma unroll
        for (int r = 0; r < 4; r++) {
            int nd = wid + 8 * r;
            int node = nb + nd;
            float4 v = *reinterpret_cast<const float4*>(ssm + nd * 132 + lane * 4);
            if (node < n_nodes)
                reinterpret_cast<float4*>(out_s + (size_t)node * 128)[lane] = v;
        }
        __syncthreads();

        // ===== Phase E: gated vector output =====
#pragma unroll
        for (int r = 0; r < 6; r++) {
            int i = t + 256 * r;
            int nd = i / 48, j = i - nd * 48;
            int o = j / 3, x = j - o * 3;
            float a = 0.f;
#pragma unroll
            for (int h = 0; h < 16; h++)
                a += vh[nd * 50 + x * 16 + h] * sWup[o * 16 + h];
            int node = nb + nd;
            if (node < n_nodes)
                out_v[(size_t)node * 48 + j] = a * gsig[nd * 16 + o];
        }
        __syncthreads();
    }
}

extern "C" void kernel_launch(void* const* d_in, const int* in_sizes, int n_in,
                              void* d_out, int out_size) {
    const float* scalar = (const float*)d_in[0];
    const float* vector = (const float*)d_in[1];
    const int*   ei     = (const int*)d_in[2];
    const float* frames = (const float*)d_in[3];
    const float* W_down = (const float*)d_in[4];
    const float* W_df   = (const float*)d_in[5];
    const float* W_so   = (const float*)d_in[6];
    const float* b_so   = (const float*)d_in[7];
    const float* W_up   = (const float*)d_in[8];
    const float* W_g    = (const float*)d_in[9];
    const float* b_g    = (const float*)d_in[10];

    int n = in_sizes[0] / S_IN;
    int e = in_sizes[2] / 2;

    float* out_s = (float*)d_out;
    float* out_v = out_s + (size_t)n * S_OUT;

    size_t pre_jobs = (size_t)NREP * n * 4;
    if (pre_jobs < (size_t)n) pre_jobs = n;
    if (pre_jobs < (size_t)K_MERGED * 128) pre_jobs = K_MERGED * 128;

    k_pre<<<(int)((pre_jobs + 255) / 256), 256>>>(vector, W_df, W_so, W_g, n);
    k_edge<<<(e + 255) / 256, 256>>>(ei, frames, e, n);
    k_fold<<<(n + 255) / 256, 256>>>(n);
    k_post<<<592, 256>>>(scalar, vector, W_down, b_so, W_up, b_g,
                         out_s, out_v, n);
}